// round 1
// baseline (speedup 1.0000x reference)
#include <cuda_runtime.h>
#include <math.h>

#define C 128
#define H 256
#define W 256
#define HW (H * W)
#define YA 16
#define XA 16

// Scratch for per-channel prefetch-tile stats (no allocations allowed).
__device__ float g_pmean[C];
__device__ float g_pstd[C];

// PyTorch bicubic convolution kernel, a = -0.75
__device__ __forceinline__ float cubic_w(float t) {
    const float a = -0.75f;
    float at = fabsf(t);
    float nr = ((a + 2.f) * at - (a + 3.f)) * at * at + 1.f;
    float fr = (((at - 5.f) * at + 8.f) * at - 4.f) * a;
    return at <= 1.f ? nr : (at < 2.f ? fr : 0.f);
}

// Row of the (out_size=3*S, in_size=4) bicubic weight matrix with index
// clamping folded in (weights accumulate at clamped indices 0..3).
__device__ __forceinline__ void bicubic_w4(int o_full, float inv_out_times_in, float w[4]) {
    float src = ((float)o_full + 0.5f) * inv_out_times_in - 0.5f;
    float fi0 = floorf(src);
    float t = src - fi0;
    int b = (int)fi0;
    w[0] = w[1] = w[2] = w[3] = 0.f;
#pragma unroll
    for (int k = -1; k <= 2; k++) {
        int idx = b + k;
        idx = idx < 0 ? 0 : (idx > 3 ? 3 : idx);
        w[idx] += cubic_w(t - (float)k);
    }
}

// Kernel 1: per-channel sum / sumsq over pre_x (x[1]); one block per channel.
__global__ void __launch_bounds__(512) stats_kernel(const float* __restrict__ x) {
    int c = blockIdx.x;
    const float4* px = (const float4*)(x + (size_t)(C + c) * HW);
    float s = 0.f, s2 = 0.f;
    for (int i = threadIdx.x; i < HW / 4; i += blockDim.x) {
        float4 v = px[i];
        s += (v.x + v.y) + (v.z + v.w);
        s2 += (v.x * v.x + v.y * v.y) + (v.z * v.z + v.w * v.w);
    }
#pragma unroll
    for (int off = 16; off; off >>= 1) {
        s += __shfl_xor_sync(0xffffffffu, s, off);
        s2 += __shfl_xor_sync(0xffffffffu, s2, off);
    }
    __shared__ float ws[32], ws2[32];
    int lane = threadIdx.x & 31, wid = threadIdx.x >> 5;
    if (lane == 0) { ws[wid] = s; ws2[wid] = s2; }
    __syncthreads();
    if (wid == 0) {
        int nw = blockDim.x >> 5;
        s = lane < nw ? ws[lane] : 0.f;
        s2 = lane < nw ? ws2[lane] : 0.f;
#pragma unroll
        for (int off = 16; off; off >>= 1) {
            s += __shfl_xor_sync(0xffffffffu, s, off);
            s2 += __shfl_xor_sync(0xffffffffu, s2, off);
        }
        if (lane == 0) {
            float n = (float)HW;
            float mean = s / n;
            float var = (s2 - n * mean * mean) / (n - 1.f);  // unbiased
            g_pmean[c] = mean;
            g_pstd[c] = sqrtf(var);
        }
    }
}

// Kernel 2: per (channel, 32-row chunk). Builds 4x4 patch + separable
// row-projections in SMEM, then normalizes both halves with float4 I/O.
__global__ void __launch_bounds__(256) norm_kernel(
    const float* __restrict__ x,
    const float* __restrict__ mtab,
    const float* __restrict__ stab,
    const float* __restrict__ weight,
    const float* __restrict__ bias,
    const int* __restrict__ d_ya,
    const int* __restrict__ d_xa,
    const int* __restrict__ d_pya,
    const int* __restrict__ d_pxa,
    float* __restrict__ out)
{
    __shared__ float rowm[4][W];   // y-patch-row projected onto output cols (mean)
    __shared__ float rowsi[4][W];  // same for 1/std
    __shared__ float pm[16], psi[16];

    int c = blockIdx.x;
    int tid = threadIdx.y * 64 + threadIdx.x;  // 0..255

    // --- Phase A: gather the 4x4 anchor patch (with pre-stat substitution)
    if (tid < 16) {
        int j = tid >> 2, i = tid & 3;
        int yst = min(max(*d_ya, 0), YA - 1);   // dynamic_slice start clamp
        int xst = min(max(*d_xa, 0), XA - 1);
        int ry = min(max(yst + j - 1, 0), YA - 1);  // edge padding (left=1)
        int rx = min(max(xst + i - 1, 0), XA - 1);
        float mv, sv;
        if (ry == *d_pya && rx == *d_pxa) {
            mv = g_pmean[c];
            sv = g_pstd[c];
        } else {
            mv = mtab[(ry * XA + rx) * C + c];
            sv = stab[(ry * XA + rx) * C + c];
        }
        pm[tid] = mv;
        psi[tid] = 1.f / sv;
    }
    __syncthreads();

    // --- Phase B: project patch columns through Wx for every output column.
    // Full bicubic matrix is (3W, 4); the center crop takes rows [W/2, W/2+W).
    {
        const float inv = 4.0f / (3.0f * (float)W);
        float wx[4];
        bicubic_w4(tid + W / 2, inv, wx);
#pragma unroll
        for (int y = 0; y < 4; y++) {
            rowm[y][tid] = pm[y * 4 + 0] * wx[0] + pm[y * 4 + 1] * wx[1] +
                           pm[y * 4 + 2] * wx[2] + pm[y * 4 + 3] * wx[3];
            rowsi[y][tid] = psi[y * 4 + 0] * wx[0] + psi[y * 4 + 1] * wx[1] +
                            psi[y * 4 + 2] * wx[2] + psi[y * 4 + 3] * wx[3];
        }
    }
    __syncthreads();

    // --- Phase C: stream 32 rows, normalize real + pre halves.
    int tx = threadIdx.x;        // 0..63 -> 4 cols each
    int ty = threadIdx.y;        // 0..3  -> row phase
    int col = tx * 4;
    float wgt = weight[c];
    float bs = bias[c];
    float pmean = g_pmean[c];
    float psinv = 1.f / g_pstd[c];

    const float* xr = x + (size_t)c * HW;
    const float* xp = x + (size_t)(C + c) * HW;
    float* outr = out + (size_t)c * HW;
    float* outp = out + (size_t)(C + c) * HW;

    const float invy = 4.0f / (3.0f * (float)H);
    int r0 = blockIdx.y * 32;

    for (int r = r0 + ty; r < r0 + 32; r += 4) {
        float wy[4];
        bicubic_w4(r + H / 2, invy, wy);

        float m[4], si[4];
#pragma unroll
        for (int j = 0; j < 4; j++) {
            m[j] = wy[0] * rowm[0][col + j] + wy[1] * rowm[1][col + j] +
                   wy[2] * rowm[2][col + j] + wy[3] * rowm[3][col + j];
            si[j] = wy[0] * rowsi[0][col + j] + wy[1] * rowsi[1][col + j] +
                    wy[2] * rowsi[2][col + j] + wy[3] * rowsi[3][col + j];
        }

        float4 vr = *(const float4*)(xr + (size_t)r * W + col);
        float4 vp = *(const float4*)(xp + (size_t)r * W + col);
        float4 orv, opv;
        orv.x = (vr.x - m[0]) * si[0] * wgt + bs;
        orv.y = (vr.y - m[1]) * si[1] * wgt + bs;
        orv.z = (vr.z - m[2]) * si[2] * wgt + bs;
        orv.w = (vr.w - m[3]) * si[3] * wgt + bs;
        opv.x = (vp.x - pmean) * psinv * wgt + bs;
        opv.y = (vp.y - pmean) * psinv * wgt + bs;
        opv.z = (vp.z - pmean) * psinv * wgt + bs;
        opv.w = (vp.w - pmean) * psinv * wgt + bs;
        *(float4*)(outr + (size_t)r * W + col) = orv;
        *(float4*)(outp + (size_t)r * W + col) = opv;
    }
}

extern "C" void kernel_launch(void* const* d_in, const int* in_sizes, int n_in,
                              void* d_out, int out_size) {
    const float* x = (const float*)d_in[0];        // (2, C, H, W)
    const float* mtab = (const float*)d_in[1];     // (YA, XA, C)
    const float* stab = (const float*)d_in[2];     // (YA, XA, C)
    const float* weight = (const float*)d_in[3];   // (1, C, 1, 1)
    const float* bias = (const float*)d_in[4];     // (1, C, 1, 1)
    const int* ya = (const int*)d_in[5];           // y_anchor
    const int* xa = (const int*)d_in[6];           // x_anchor
    const int* pya = (const int*)d_in[7];          // pre_y1_anchor
    const int* pxa = (const int*)d_in[8];          // pre_x1_anchor
    float* out = (float*)d_out;

    stats_kernel<<<C, 512>>>(x);
    norm_kernel<<<dim3(C, 8), dim3(64, 4)>>>(x, mtab, stab, weight, bias,
                                             ya, xa, pya, pxa, out);
}